// round 8
// baseline (speedup 1.0000x reference)
#include <cuda_runtime.h>
#include <cuda_bf16.h>
#include <cuda_fp16.h>
#include <cstdint>

#define NMAX 100000
#define EMAX 1600000

// Scratch (device globals — allocation-free per harness rules)
__device__ float  g_H[NMAX * 128];     // node features (post-layer, fp32)
__device__ __half g_Mh[NMAX * 128];    // messages: (h @ W) * dinv[row], fp16
__device__ float  g_dinv[NMAX];
__device__ int    g_deg[NMAX];
__device__ int    g_cur[NMAX];
__device__ int    g_rptr[NMAX + 1];
__device__ int    g_col[EMAX];
__device__ int    g_src[EMAX];
__device__ int    g_dst[EMAX];
__device__ int    g_batch[NMAX];
__device__ int    g_is64;

// Pre-converted bf16 W images, B-layout [n][k] with rows padded to 136 halves.
#define BROW 136
__device__ __align__(16) unsigned short g_Wb[3][2][128 * BROW];

__device__ __forceinline__ uint32_t packbf(float x0, float x1) {
    return ((uint32_t)__bfloat16_as_ushort(__float2bfloat16(x1)) << 16)
         |  (uint32_t)__bfloat16_as_ushort(__float2bfloat16(x0));
}

// ===================== dtype probe =====================
__global__ void k_detect(const void* edge, int E) {
    const long long* e64 = (const long long*)edge;
    int ok = 1;
    for (int i = 0; i < 8; i++) {
        long long v = e64[i];
        if (v < 0 || v >= (1LL << 31)) ok = 0;
    }
    g_is64 = ok;
}

// ===================== zero counters =====================
__global__ void k_zero(int N) {
    int i = blockIdx.x * blockDim.x + threadIdx.x;
    if (i < N) { g_deg[i] = 0; g_cur[i] = 0; }
}

// ===================== edge convert + degree histogram (fused) =====================
__global__ void k_cvt_edge_deg(const void* edge, int E, int N) {
    int i = blockIdx.x * blockDim.x + threadIdx.x;
    if (i >= E) return;
    int s, d;
    if (g_is64) {
        const long long* e = (const long long*)edge;
        s = (int)e[i];
        d = (int)e[E + i];
    } else {
        const int* e = (const int*)edge;
        s = e[i];
        d = e[E + i];
    }
    g_src[i] = s;
    g_dst[i] = d;
    if ((unsigned)d < (unsigned)N) atomicAdd(&g_deg[d], 1);
}

__global__ void k_cvt_batch(const void* batch, int N) {
    int i = blockIdx.x * blockDim.x + threadIdx.x;
    if (i >= N) return;
    g_batch[i] = g_is64 ? (int)((const long long*)batch)[i]
                        : ((const int*)batch)[i];
}

// ===================== exclusive scan -> g_rptr + dinv (fused, single block) =====================
__global__ void __launch_bounds__(1024) k_scan_dinv(int N) {
    __shared__ int ssum[1024];
    int t = threadIdx.x;
    int per = (N + 1023) / 1024;
    int begin = t * per;
    int end   = begin + per; if (end > N) end = N; if (begin > N) begin = N;
    int s = 0;
    for (int i = begin; i < end; i++) {
        int dg = g_deg[i];
        s += dg;
        g_dinv[i] = rsqrtf((float)(dg + 1));   // +1 self-loop
    }
    ssum[t] = s;
    __syncthreads();
    for (int off = 1; off < 1024; off <<= 1) {
        int v = (t >= off) ? ssum[t - off] : 0;
        __syncthreads();
        ssum[t] += v;
        __syncthreads();
    }
    int run = (t == 0) ? 0 : ssum[t - 1];
    for (int i = begin; i < end; i++) { g_rptr[i] = run; run += g_deg[i]; }
    if (t == 1023) g_rptr[N] = run;
}

// ===================== CSR fill =====================
__global__ void k_fill(int E, int N) {
    int i = blockIdx.x * blockDim.x + threadIdx.x;
    if (i >= E) return;
    unsigned d = (unsigned)g_dst[i];
    unsigned s = (unsigned)g_src[i];
    if (d >= (unsigned)N || s >= (unsigned)N) return;
    int pos = atomicAdd(&g_cur[d], 1);
    g_col[g_rptr[d] + pos] = (int)s;
}

// ===================== W -> bf16 hi/lo images in B layout [n][k] =====================
__global__ void k_wconv(const float* __restrict__ conv_w) {
    int l = blockIdx.y;
    int c = blockIdx.x * 8;    // k group of 8
    int n = threadIdx.x;       // 0..127
    const float* W = conv_w + (size_t)l * 16384;
    uint32_t hi[4], lo[4];
#pragma unroll
    for (int j = 0; j < 4; j++) {
        float v0 = W[(size_t)(c + 2 * j) * 128 + n];
        float v1 = W[(size_t)(c + 2 * j + 1) * 128 + n];
        float h0 = __bfloat162float(__float2bfloat16(v0));
        float h1 = __bfloat162float(__float2bfloat16(v1));
        hi[j] = packbf(v0, v1);
        lo[j] = packbf(v0 - h0, v1 - h1);
    }
    *(uint4*)&g_Wb[l][0][n * BROW + c] = make_uint4(hi[0], hi[1], hi[2], hi[3]);
    *(uint4*)&g_Wb[l][1][n * BROW + c] = make_uint4(lo[0], lo[1], lo[2], lo[3]);
}

// ===================== mma.sync GEMM: Mh = (Hin @ W) * dinv[row] (fp16 out) =====================
#define TILE_H (128 * BROW)

__global__ void __launch_bounds__(256, 1) k_gemm_mma(const float* __restrict__ xin,
                                                     int layer, int N, int useH) {
    extern __shared__ unsigned short sm[];
    const float* __restrict__ Hin = useH ? (const float*)g_H : xin;

    int tid  = threadIdx.x;
    int lane = tid & 31;
    int wid  = tid >> 5;
    int row0 = blockIdx.x * 128;

    unsigned short* Ah = sm;
    unsigned short* Al = sm + TILE_H;
    unsigned short* Bh = sm + 2 * TILE_H;
    unsigned short* Bl = sm + 3 * TILE_H;

    // ---- stage A: fp32 -> bf16 hi/lo ----
#pragma unroll
    for (int i = 0; i < 8; i++) {
        int j = tid + i * 256;
        int r = j >> 4;
        int c = (j & 15) << 3;
        float v[8];
        if (row0 + r < N) {
            float4 a = *(const float4*)(Hin + (size_t)(row0 + r) * 128 + c);
            float4 b = *(const float4*)(Hin + (size_t)(row0 + r) * 128 + c + 4);
            v[0] = a.x; v[1] = a.y; v[2] = a.z; v[3] = a.w;
            v[4] = b.x; v[5] = b.y; v[6] = b.z; v[7] = b.w;
        } else {
#pragma unroll
            for (int q = 0; q < 8; q++) v[q] = 0.f;
        }
        uint32_t hi[4], lo[4];
#pragma unroll
        for (int q = 0; q < 4; q++) {
            float x0 = v[2 * q], x1 = v[2 * q + 1];
            float h0 = __bfloat162float(__float2bfloat16(x0));
            float h1 = __bfloat162float(__float2bfloat16(x1));
            hi[q] = packbf(x0, x1);
            lo[q] = packbf(x0 - h0, x1 - h1);
        }
        *(uint4*)&Ah[r * BROW + c] = make_uint4(hi[0], hi[1], hi[2], hi[3]);
        *(uint4*)&Al[r * BROW + c] = make_uint4(lo[0], lo[1], lo[2], lo[3]);
    }

    // ---- copy W images ----
    {
        const uint4* wh = (const uint4*)g_Wb[layer][0];
        const uint4* wl = (const uint4*)g_Wb[layer][1];
        uint4* bh = (uint4*)Bh;
        uint4* bl = (uint4*)Bl;
        for (int j = tid; j < (TILE_H / 8); j += 256) {
            bh[j] = wh[j];
            bl[j] = wl[j];
        }
    }
    __syncthreads();

    int wm = wid & 3;
    int wn = wid >> 2;
    int m0 = wm * 32;
    int n0 = wn * 64;
    int gid = lane >> 2;
    int tig = lane & 3;

    float acc[2][8][4];
#pragma unroll
    for (int mf = 0; mf < 2; mf++)
#pragma unroll
        for (int nf = 0; nf < 8; nf++)
#pragma unroll
            for (int q = 0; q < 4; q++) acc[mf][nf][q] = 0.f;

    for (int s = 0; s < 3; s++) {
        const unsigned short* Asel = (s == 2) ? Al : Ah;
        const unsigned short* Bsel = (s == 1) ? Bl : Bh;
#pragma unroll
        for (int k = 0; k < 8; k++) {
            int k0 = k * 16;
            uint32_t a[2][4];
#pragma unroll
            for (int mf = 0; mf < 2; mf++) {
                int rr = m0 + mf * 16;
                a[mf][0] = *(const uint32_t*)&Asel[(rr + gid)     * BROW + k0 + tig * 2];
                a[mf][1] = *(const uint32_t*)&Asel[(rr + gid + 8) * BROW + k0 + tig * 2];
                a[mf][2] = *(const uint32_t*)&Asel[(rr + gid)     * BROW + k0 + 8 + tig * 2];
                a[mf][3] = *(const uint32_t*)&Asel[(rr + gid + 8) * BROW + k0 + 8 + tig * 2];
            }
            uint32_t b[8][2];
#pragma unroll
            for (int nf = 0; nf < 8; nf++) {
                int n = n0 + nf * 8 + gid;
                b[nf][0] = *(const uint32_t*)&Bsel[n * BROW + k0 + tig * 2];
                b[nf][1] = *(const uint32_t*)&Bsel[n * BROW + k0 + 8 + tig * 2];
            }
#pragma unroll
            for (int mf = 0; mf < 2; mf++)
#pragma unroll
                for (int nf = 0; nf < 8; nf++) {
                    asm volatile(
                        "mma.sync.aligned.m16n8k16.row.col.f32.bf16.bf16.f32 "
                        "{%0,%1,%2,%3}, {%4,%5,%6,%7}, {%8,%9}, {%0,%1,%2,%3};"
                        : "+f"(acc[mf][nf][0]), "+f"(acc[mf][nf][1]),
                          "+f"(acc[mf][nf][2]), "+f"(acc[mf][nf][3])
                        : "r"(a[mf][0]), "r"(a[mf][1]), "r"(a[mf][2]), "r"(a[mf][3]),
                          "r"(b[nf][0]), "r"(b[nf][1]));
                }
        }
    }

    // ---- epilogue: D * dinv -> g_Mh (fp16) ----
#pragma unroll
    for (int mf = 0; mf < 2; mf++) {
        int r1 = row0 + m0 + mf * 16 + gid;
        int r2 = r1 + 8;
        float dv1 = (r1 < N) ? g_dinv[r1] : 0.f;
        float dv2 = (r2 < N) ? g_dinv[r2] : 0.f;
#pragma unroll
        for (int nf = 0; nf < 8; nf++) {
            int c = n0 + nf * 8 + tig * 2;
            if (r1 < N)
                *(__half2*)(g_Mh + (size_t)r1 * 128 + c) =
                    __floats2half2_rn(acc[mf][nf][0] * dv1, acc[mf][nf][1] * dv1);
            if (r2 < N)
                *(__half2*)(g_Mh + (size_t)r2 * 128 + c) =
                    __floats2half2_rn(acc[mf][nf][2] * dv2, acc[mf][nf][3] * dv2);
        }
    }
}

// ===================== gather aggregation + bias + relu (fp16 messages) =====================
// H[d] = relu( dinv[d] * ( Mh[d] + sum_{e: dst=d} Mh[src_e] ) + b )
__device__ __forceinline__ float4 ld_m4(const uint2* M2, size_t idx, int lane) {
    uint2 u = M2[idx * 32 + lane];
    float2 f01 = __half22float2(*(__half2*)&u.x);
    float2 f23 = __half22float2(*(__half2*)&u.y);
    return make_float4(f01.x, f01.y, f23.x, f23.y);
}

__global__ void __launch_bounds__(256) k_gather(const float* __restrict__ b, int N) {
    int w = (blockIdx.x * 256 + threadIdx.x) >> 5;
    if (w >= N) return;
    int lane = threadIdx.x & 31;

    int s0 = g_rptr[w], s1 = g_rptr[w + 1];
    float dv = g_dinv[w];
    const uint2* M2 = (const uint2*)g_Mh;

    float4 acc = ld_m4(M2, (size_t)w, lane);   // self-loop message (pre-scaled by dinv[w])

    int e = s0;
    for (; e + 3 < s1; e += 4) {
        int sa = g_col[e], sb = g_col[e + 1], sc = g_col[e + 2], sd = g_col[e + 3];
        float4 va = ld_m4(M2, (size_t)sa, lane);
        float4 vb = ld_m4(M2, (size_t)sb, lane);
        float4 vc = ld_m4(M2, (size_t)sc, lane);
        float4 vd = ld_m4(M2, (size_t)sd, lane);
        acc.x += va.x + vb.x + vc.x + vd.x;
        acc.y += va.y + vb.y + vc.y + vd.y;
        acc.z += va.z + vb.z + vc.z + vd.z;
        acc.w += va.w + vb.w + vc.w + vd.w;
    }
    for (; e < s1; e++) {
        float4 v = ld_m4(M2, (size_t)g_col[e], lane);
        acc.x += v.x; acc.y += v.y; acc.z += v.z; acc.w += v.w;
    }

    float4 bb = ((const float4*)b)[lane];
    float4 o;
    o.x = fmaxf(acc.x * dv + bb.x, 0.f);
    o.y = fmaxf(acc.y * dv + bb.y, 0.f);
    o.z = fmaxf(acc.z * dv + bb.z, 0.f);
    o.w = fmaxf(acc.w * dv + bb.w, 0.f);
    ((float4*)g_H)[(size_t)w * 32 + lane] = o;
}

// ===================== fused pooling + output linear =====================
__global__ void __launch_bounds__(128) k_pool_out(const float* __restrict__ out_w,
                                                  const float* __restrict__ out_b,
                                                  float* __restrict__ out, int N) {
    int g = blockIdx.x;
    int d = threadIdx.x;

    int lo, hi;
    { int a = 0, b = N; while (a < b) { int m = (a + b) >> 1; if (g_batch[m] < g) a = m + 1; else b = m; } lo = a; }
    { int a = lo, b = N; while (a < b) { int m = (a + b) >> 1; if (g_batch[m] < g + 1) a = m + 1; else b = m; } hi = a; }

    float s = 0.f, mx = 0.f;   // relu output >= 0: max init 0 matches segment_max for non-empty segments
    for (int n = lo; n < hi; n++) {
        float v = g_H[(size_t)n * 128 + d];
        s += v;
        mx = fmaxf(mx, v);
    }
    float cnt  = fmaxf((float)(hi - lo), 1.f);
    float mean = s / cnt;

    __shared__ float sp[128][10];
#pragma unroll
    for (int j = 0; j < 10; j++)
        sp[d][j] = mx * out_w[d * 10 + j]
                 + mean * out_w[(128 + d) * 10 + j]
                 + s * out_w[(256 + d) * 10 + j];
    __syncthreads();

    if (d < 10) {
        float r = 0.f;
        for (int i = 0; i < 128; i++) r += sp[i][d];
        out[g * 10 + d] = r + out_b[d];
    }
}

// ===================== launch =====================
extern "C" void kernel_launch(void* const* d_in, const int* in_sizes, int n_in,
                              void* d_out, int out_size) {
    const float* x      = (const float*)d_in[0];
    const void*  edge   = d_in[1];
    const void*  batch  = d_in[2];
    const float* conv_w = (const float*)d_in[3];
    const float* conv_b = (const float*)d_in[4];
    const float* out_w  = (const float*)d_in[5];
    const float* out_b  = (const float*)d_in[6];
    float*       out    = (float*)d_out;

    int N = in_sizes[0] / 128;
    int E = in_sizes[1] / 2;

    const int SMEM_BYTES = 4 * TILE_H * 2;   // 139264
    static bool attr_done = false;
    if (!attr_done) {
        cudaFuncSetAttribute(k_gemm_mma, cudaFuncAttributeMaxDynamicSharedMemorySize, SMEM_BYTES);
        attr_done = true;
    }

    k_detect<<<1, 1>>>(edge, E);
    k_zero<<<(N + 255) / 256, 256>>>(N);
    k_cvt_edge_deg<<<(E + 255) / 256, 256>>>(edge, E, N);
    k_cvt_batch<<<(N + 255) / 256, 256>>>(batch, N);
    k_scan_dinv<<<1, 1024>>>(N);
    k_fill<<<(E + 255) / 256, 256>>>(E, N);
    k_wconv<<<dim3(16, 3), 128>>>(conv_w);

    int tiles = (N + 127) / 128;
    for (int l = 0; l < 3; l++) {
        k_gemm_mma<<<tiles, 256, SMEM_BYTES>>>(x, l, N, l > 0 ? 1 : 0);
        k_gather<<<(N * 32 + 255) / 256, 256>>>(conv_b + l * 128, N);
    }

    k_pool_out<<<256, 128>>>(out_w, out_b, out, N);
}